// round 1
// baseline (speedup 1.0000x reference)
#include <cuda_runtime.h>
#include <cuda_bf16.h>

#define CIN   256
#define COUT  256
#define HH    32
#define WW    32
#define NB    4

#define CI_CHUNK      8
#define CO_PER_BLOCK  16
#define CO_PER_THREAD 4
#define PX_PER_THREAD 16
#define THREADS       256

// Shared x tile: CI_CHUNK channels of (32+2)x(32+2) halo-padded input.
// Row stride 35 makes the (16 rows x 2 half-rows) lane access pattern
// conflict-free (3r + 16h + d covers all 32 banks).
#define XROW 35

__global__ __launch_bounds__(THREADS, 2)
void mixed_conv3x3_kernel(const float* __restrict__ x,
                          const int*   __restrict__ sample_arc,
                          const float* __restrict__ Wt,
                          const float* __restrict__ bias,
                          float*       __restrict__ out)
{
    __shared__ float xs[CI_CHUNK][34][XROW];
    __shared__ float ws[CO_PER_BLOCK][CI_CHUNK][9];

    const int tid     = threadIdx.x;
    const int b       = blockIdx.y;          // sample
    const int co_base = blockIdx.x * CO_PER_BLOCK;
    const int a       = __ldg(&sample_arc[b]);

    // thread -> (4 output channels) x (16 contiguous pixels in one row)
    const int co_sub  = tid >> 6;            // 0..3
    const int g       = tid & 63;
    const int row     = g >> 1;              // 0..31
    const int colbase = (g & 1) << 4;        // 0 or 16

    float acc[CO_PER_THREAD][PX_PER_THREAD];
#pragma unroll
    for (int j = 0; j < CO_PER_THREAD; j++)
#pragma unroll
        for (int p = 0; p < PX_PER_THREAD; p++)
            acc[j][p] = 0.0f;

    const float* xb = x  + (size_t)b * CIN * (HH * WW);
    const float* Wb = Wt + (size_t)a * COUT * (CIN * 9);

    for (int ci0 = 0; ci0 < CIN; ci0 += CI_CHUNK) {
        __syncthreads();   // previous-iteration consumers done before overwrite

        // ---- stage input tile: CI_CHUNK x 34 x 34 (halo, zero-padded) ----
        for (int idx = tid; idx < CI_CHUNK * 34 * 34; idx += THREADS) {
            int c  = idx / (34 * 34);
            int r  = (idx / 34) % 34;
            int w_ = idx % 34;
            int gh = r - 1, gw = w_ - 1;
            float v = 0.0f;
            if ((unsigned)gh < (unsigned)HH && (unsigned)gw < (unsigned)WW)
                v = __ldg(&xb[(size_t)(ci0 + c) * (HH * WW) + gh * WW + gw]);
            xs[c][r][w_] = v;
        }

        // ---- stage weight tile: 16co x 8ci x 9 ----
        for (int idx = tid; idx < CO_PER_BLOCK * CI_CHUNK * 9; idx += THREADS) {
            int co  = idx / (CI_CHUNK * 9);
            int rem = idx % (CI_CHUNK * 9);
            int ci  = rem / 9;
            int k   = rem % 9;
            ws[co][ci][k] =
                __ldg(&Wb[(size_t)(co_base + co) * (CIN * 9) + (ci0 + ci) * 9 + k]);
        }
        __syncthreads();

        // ---- compute: keep ci/kh loops rolled (I-cache), inner fully unrolled ----
#pragma unroll 1
        for (int ci = 0; ci < CI_CHUNK; ci++) {
#pragma unroll 1
            for (int kh = 0; kh < 3; kh++) {
                float xr[18];
#pragma unroll
                for (int d = 0; d < 18; d++)
                    xr[d] = xs[ci][row + kh][colbase + d];

                float wv[CO_PER_THREAD][3];
#pragma unroll
                for (int j = 0; j < CO_PER_THREAD; j++)
#pragma unroll
                    for (int kw = 0; kw < 3; kw++)
                        wv[j][kw] = ws[co_sub * CO_PER_THREAD + j][ci][kh * 3 + kw];

#pragma unroll
                for (int j = 0; j < CO_PER_THREAD; j++)
#pragma unroll
                    for (int kw = 0; kw < 3; kw++)
#pragma unroll
                        for (int p = 0; p < PX_PER_THREAD; p++)
                            acc[j][p] = fmaf(wv[j][kw], xr[p + kw], acc[j][p]);
            }
        }
    }

    // ---- epilogue: bias + vectorized store ----
#pragma unroll
    for (int j = 0; j < CO_PER_THREAD; j++) {
        int co   = co_base + co_sub * CO_PER_THREAD + j;
        float bb = __ldg(&bias[a * COUT + co]);
        float4* o4 = (float4*)(out + ((size_t)b * COUT + co) * (HH * WW)
                               + row * WW + colbase);
#pragma unroll
        for (int q = 0; q < 4; q++) {
            float4 v;
            v.x = acc[j][4 * q + 0] + bb;
            v.y = acc[j][4 * q + 1] + bb;
            v.z = acc[j][4 * q + 2] + bb;
            v.w = acc[j][4 * q + 3] + bb;
            o4[q] = v;
        }
    }
}

extern "C" void kernel_launch(void* const* d_in, const int* in_sizes, int n_in,
                              void* d_out, int out_size)
{
    const float* x    = (const float*)d_in[0];   // [64,256,32,32]
    const int*   arc  = (const int*)  d_in[1];   // [64]
    const float* W    = (const float*)d_in[2];   // [4,256,256,3,3]
    const float* bias = (const float*)d_in[3];   // [4,256]
    float*       out  = (float*)d_out;           // [64,256,32,32]

    dim3 grid(COUT / CO_PER_BLOCK, 64);          // (16, 64)
    mixed_conv3x3_kernel<<<grid, THREADS>>>(x, arc, W, bias, out);
}

// round 4
// speedup vs baseline: 3.6722x; 3.6722x over previous
#include <cuda_runtime.h>
#include <cuda_bf16.h>
#include <cstdint>

#define BATCH 64
#define CIN   256
#define COUT  256
#define HH    32
#define WW    32
#define NB    4
#define NTAP  9

#define THREADS 256
#define CI_CHUNK 16            // ci per K-chunk (8 bf16x2 pairs)
#define NPAIR    8
#define ROWS_PER_CTA 4         // image rows per CTA (128 px)

// ---- smem word layout (uint32 units) ----
// ws planes: [tap][co 128][pair 8 (+1 pad)] -> stride 9 words per co
#define WS_WORDS (NTAP * 128 * 9)          // 10368
// xs planes: [pair 8][row 6][col 34]
#define XS_WORDS (NPAIR * 6 * 34)          // 1632
#define SMEM_WORDS (2 * WS_WORDS + 2 * XS_WORDS)   // 24000 -> 96000 B

// ---- device scratch: prepacked weights ----
// layout: [g][co_half][tap][pair 128][co_local 128]  (u32 = bf16x2 over ci pair)
#define WPK_ELEMS (NB * 2 * NTAP * 128 * 128)
__device__ uint32_t g_wpk_hi[WPK_ELEMS];
__device__ uint32_t g_wpk_lo[WPK_ELEMS];

__device__ __forceinline__ uint32_t pack_bf16x2(__nv_bfloat16 e, __nv_bfloat16 o) {
    uint16_t le = *(uint16_t*)&e, lo = *(uint16_t*)&o;
    return (uint32_t)le | ((uint32_t)lo << 16);
}

// =============== pre-pass: reorder + hi/lo split + pack ===============
__global__ void prep_weights(const float* __restrict__ W) {
    int i = blockIdx.x * blockDim.x + threadIdx.x;   // [0, NB*2*128*128)
    if (i >= NB * 2 * 128 * 128) return;
    int co_l = i & 127;
    int pi   = (i >> 7) & 127;
    int ch   = (i >> 14) & 1;
    int g    = i >> 15;
    int co   = ch * 128 + co_l;
    // W: [g][co][ci][3][3]; ci = 2*pi, 2*pi+1 -> 18 contiguous floats
    const float* src = W + (((size_t)(g * COUT + co) * CIN + 2 * pi) * NTAP);
#pragma unroll
    for (int tap = 0; tap < NTAP; tap++) {
        float ve = src[tap], vo = src[NTAP + tap];
        __nv_bfloat16 he = __float2bfloat16_rn(ve);
        __nv_bfloat16 ho = __float2bfloat16_rn(vo);
        __nv_bfloat16 le = __float2bfloat16_rn(ve - __bfloat162float(he));
        __nv_bfloat16 lo = __float2bfloat16_rn(vo - __bfloat162float(ho));
        size_t dst = ((((size_t)(g * 2 + ch) * NTAP + tap) * 128 + pi) * 128 + co_l);
        g_wpk_hi[dst] = pack_bf16x2(he, ho);
        g_wpk_lo[dst] = pack_bf16x2(le, lo);
    }
}

// =============== mma wrapper ===============
__device__ __forceinline__ void mma_bf16(float* d, const uint32_t* a, uint32_t b0, uint32_t b1) {
    asm volatile(
        "mma.sync.aligned.m16n8k16.row.col.f32.bf16.bf16.f32 "
        "{%0,%1,%2,%3}, {%4,%5,%6,%7}, {%8,%9}, {%0,%1,%2,%3};"
        : "+f"(d[0]), "+f"(d[1]), "+f"(d[2]), "+f"(d[3])
        : "r"(a[0]), "r"(a[1]), "r"(a[2]), "r"(a[3]), "r"(b0), "r"(b1));
}

// =============== main kernel ===============
__global__ __launch_bounds__(THREADS, 2)
void conv_mma(const float* __restrict__ x, const int* __restrict__ arc,
              const float* __restrict__ bias, float* __restrict__ out)
{
    extern __shared__ uint32_t smem[];
    uint32_t* ws_hi = smem;                       // [tap][co][9]
    uint32_t* ws_lo = smem + WS_WORDS;
    uint32_t* xs_hi = smem + 2 * WS_WORDS;        // [pair][6][34]
    uint32_t* xs_lo = xs_hi + XS_WORDS;

    const int tid  = threadIdx.x;
    const int wid  = tid >> 5, lane = tid & 31;
    const int gi   = lane >> 2, ti = lane & 3;    // fragment group / thread-in-group
    const int b    = blockIdx.y;
    const int ch   = blockIdx.x & 1;              // co half
    const int r0   = (blockIdx.x >> 1) * ROWS_PER_CTA;
    const int g    = __ldg(&arc[b]);

    const int warp_m = wid & 3;                   // co: warp_m*32
    const int warp_n = wid >> 2;                  // rows: warp_n*2 (of 4)

    float acc[2][8][4];                           // [m-tile][n-tile][frag]
#pragma unroll
    for (int m = 0; m < 2; m++)
#pragma unroll
        for (int j = 0; j < 8; j++)
#pragma unroll
            for (int q = 0; q < 4; q++) acc[m][j][q] = 0.0f;

    const float* xb = x + (size_t)b * CIN * HH * WW;
    const uint32_t* wsrc_hi = g_wpk_hi + (size_t)(g * 2 + ch) * NTAP * 128 * 128;
    const uint32_t* wsrc_lo = g_wpk_lo + (size_t)(g * 2 + ch) * NTAP * 128 * 128;

    for (int chunk = 0; chunk < CIN / CI_CHUNK; chunk++) {
        const int ci0 = chunk * CI_CHUNK;
        const int pi0 = chunk * NPAIR;
        __syncthreads();   // previous consumers done

        // ---- stage x: [pair][6 rows][34 cols], halo zero, hi/lo planes ----
#pragma unroll
        for (int it = 0; it < 7; it++) {
            int idx = tid + it * THREADS;
            if (idx < XS_WORDS) {
                int p  = idx / 204;
                int rm = idx % 204;
                int ri = rm / 34, cs = rm % 34;
                int r = r0 - 1 + ri, c = cs - 1;
                float ve = 0.0f, vo = 0.0f;
                if ((unsigned)r < (unsigned)HH && (unsigned)c < (unsigned)WW) {
                    size_t base = ((size_t)(ci0 + 2 * p) * HH + r) * WW + c;
                    ve = __ldg(&xb[base]);
                    vo = __ldg(&xb[base + HH * WW]);
                }
                __nv_bfloat16 he = __float2bfloat16_rn(ve);
                __nv_bfloat16 ho = __float2bfloat16_rn(vo);
                __nv_bfloat16 le = __float2bfloat16_rn(ve - __bfloat162float(he));
                __nv_bfloat16 lo = __float2bfloat16_rn(vo - __bfloat162float(ho));
                xs_hi[idx] = pack_bf16x2(he, ho);
                xs_lo[idx] = pack_bf16x2(le, lo);
            }
        }

        // ---- stage weights: 9 taps x [pair 8][co 128] -> ws[tap][co][pair] ----
#pragma unroll
        for (int it = 0; it < 36; it++) {
            int idx = tid + it * THREADS;          // [0, 9216)
            int tap = idx / 1024;
            int rm  = idx & 1023;
            int p   = rm >> 7, co = rm & 127;
            size_t src = ((size_t)tap * 128 + pi0 + p) * 128 + co;
            int dst = tap * 1152 + co * 9 + p;
            ws_hi[dst] = wsrc_hi[src];
            ws_lo[dst] = wsrc_lo[src];
        }
        __syncthreads();

        // ---- compute: 9 taps x 3 passes ----
#pragma unroll 1
        for (int tap = 0; tap < NTAP; tap++) {
            const int kh = tap / 3, kw = tap % 3;
            // A fragments for both m-tiles, hi & lo
            uint32_t Ah[2][4], Al[2][4];
#pragma unroll
            for (int m = 0; m < 2; m++) {
                int cob = warp_m * 32 + m * 16;
                int base = tap * 1152 + cob * 9;
                Ah[m][0] = ws_hi[base + (gi)     * 9 + ti];
                Ah[m][1] = ws_hi[base + (gi + 8) * 9 + ti];
                Ah[m][2] = ws_hi[base + (gi)     * 9 + ti + 4];
                Ah[m][3] = ws_hi[base + (gi + 8) * 9 + ti + 4];
                Al[m][0] = ws_lo[base + (gi)     * 9 + ti];
                Al[m][1] = ws_lo[base + (gi + 8) * 9 + ti];
                Al[m][2] = ws_lo[base + (gi)     * 9 + ti + 4];
                Al[m][3] = ws_lo[base + (gi + 8) * 9 + ti + 4];
            }
#pragma unroll
            for (int j = 0; j < 8; j++) {
                int ri = warp_n * 2 + (j >> 2) + kh;       // staged row
                int cs = (j & 3) * 8 + gi + kw;            // staged col
                int o0 = (ti)     * 204 + ri * 34 + cs;
                int o1 = (ti + 4) * 204 + ri * 34 + cs;
                uint32_t bh0 = xs_hi[o0], bh1 = xs_hi[o1];
                uint32_t bl0 = xs_lo[o0], bl1 = xs_lo[o1];
#pragma unroll
                for (int m = 0; m < 2; m++) {
                    mma_bf16(acc[m][j], Ah[m], bh0, bh1);  // hi*hi
                    mma_bf16(acc[m][j], Ah[m], bl0, bl1);  // hi*lo
                    mma_bf16(acc[m][j], Al[m], bh0, bh1);  // lo*hi
                }
            }
        }
    }

    // ---- epilogue: bias + store ----
#pragma unroll
    for (int m = 0; m < 2; m++) {
        int co_l0 = warp_m * 32 + m * 16 + gi;
        float bv0 = __ldg(&bias[g * COUT + ch * 128 + co_l0]);
        float bv1 = __ldg(&bias[g * COUT + ch * 128 + co_l0 + 8]);
#pragma unroll
        for (int j = 0; j < 8; j++) {
            int row = r0 + warp_n * 2 + (j >> 2);
            int col = (j & 3) * 8 + 2 * ti;
            float* o0 = out + (((size_t)b * COUT + ch * 128 + co_l0) * HH + row) * WW + col;
            float* o1 = o0 + 8 * HH * WW;
            float2 v0 = make_float2(acc[m][j][0] + bv0, acc[m][j][1] + bv0);
            float2 v1 = make_float2(acc[m][j][2] + bv1, acc[m][j][3] + bv1);
            *(float2*)o0 = v0;
            *(float2*)o1 = v1;
        }
    }
}

// =============== launch ===============
extern "C" void kernel_launch(void* const* d_in, const int* in_sizes, int n_in,
                              void* d_out, int out_size)
{
    const float* x    = (const float*)d_in[0];   // [64,256,32,32]
    const int*   arc  = (const int*)  d_in[1];   // [64]
    const float* W    = (const float*)d_in[2];   // [4,256,256,3,3]
    const float* bias = (const float*)d_in[3];   // [4,256]
    float*       out  = (float*)d_out;           // [64,256,32,32]

    prep_weights<<<(NB * 2 * 128 * 128 + 255) / 256, 256>>>(W);

    cudaFuncSetAttribute(conv_mma, cudaFuncAttributeMaxDynamicSharedMemorySize,
                         SMEM_WORDS * 4);
    dim3 grid(2 * (HH / ROWS_PER_CTA), BATCH);   // (16, 64)
    conv_mma<<<grid, THREADS, SMEM_WORDS * 4>>>(x, arc, bias, out);
}